// round 6
// baseline (speedup 1.0000x reference)
#include <cuda_runtime.h>

// Problem constants (fixed by the reference: B=8, S=2048, D=1024)
#define BB 8
#define SS 2048
#define DD 1024
#define CHUNKS 64
#define ROWS_PER_CHUNK (SS / CHUNKS)   // 32

// Scratch (written, never accumulated -> no zero-init needed).
__device__ float g_partial[BB * CHUNKS * DD];   // 2 MB
__device__ float g_xsum[BB * DD];               // 32 KB

// ---------------------------------------------------------------------------
// Kernel A: per-(batch, chunk) column sum of x over S.
// grid = (64, 8) = 512 CTAs (~3.5 CTAs/SM -> ~28 warps/SM for latency hiding).
// block = 256; thread t owns float4 column t; each row read = 4 KB coalesced.
// 4-way row unroll -> 4 independent LDG.128 in flight per warp per iter.
// ---------------------------------------------------------------------------
__global__ __launch_bounds__(256) void colsum_kernel(const float* __restrict__ x) {
    const int c = blockIdx.x;
    const int b = blockIdx.y;
    const int t = threadIdx.x;

    const float4* __restrict__ xp =
        reinterpret_cast<const float4*>(x + ((size_t)b * SS + (size_t)c * ROWS_PER_CHUNK) * DD) + t;

    float4 a0 = make_float4(0.f, 0.f, 0.f, 0.f);
    float4 a1 = make_float4(0.f, 0.f, 0.f, 0.f);
    float4 a2 = make_float4(0.f, 0.f, 0.f, 0.f);
    float4 a3 = make_float4(0.f, 0.f, 0.f, 0.f);

    #pragma unroll
    for (int s = 0; s < ROWS_PER_CHUNK; s += 4) {
        float4 v0 = xp[(size_t)(s + 0) * (DD / 4)];
        float4 v1 = xp[(size_t)(s + 1) * (DD / 4)];
        float4 v2 = xp[(size_t)(s + 2) * (DD / 4)];
        float4 v3 = xp[(size_t)(s + 3) * (DD / 4)];
        a0.x += v0.x; a0.y += v0.y; a0.z += v0.z; a0.w += v0.w;
        a1.x += v1.x; a1.y += v1.y; a1.z += v1.z; a1.w += v1.w;
        a2.x += v2.x; a2.y += v2.y; a2.z += v2.z; a2.w += v2.w;
        a3.x += v3.x; a3.y += v3.y; a3.z += v3.z; a3.w += v3.w;
    }

    float4 acc;
    acc.x = (a0.x + a1.x) + (a2.x + a3.x);
    acc.y = (a0.y + a1.y) + (a2.y + a3.y);
    acc.z = (a0.z + a1.z) + (a2.z + a3.z);
    acc.w = (a0.w + a1.w) + (a2.w + a3.w);

    reinterpret_cast<float4*>(g_partial + ((size_t)b * CHUNKS + c) * DD)[t] = acc;
}

// ---------------------------------------------------------------------------
// Kernel B: fold the 64 chunk partials into g_xsum — done exactly once.
// grid = 8 (one CTA per batch), block = 256. Dual accumulators so pairs of
// independent loads batch ahead of the FADD chains.
// ---------------------------------------------------------------------------
__global__ __launch_bounds__(256) void reduce_kernel() {
    const int b = blockIdx.x;
    const int t = threadIdx.x;
    const float4* __restrict__ pp =
        reinterpret_cast<const float4*>(g_partial + (size_t)b * CHUNKS * DD);

    float4 e0 = make_float4(0.f, 0.f, 0.f, 0.f);
    float4 e1 = make_float4(0.f, 0.f, 0.f, 0.f);
    float4 e2 = make_float4(0.f, 0.f, 0.f, 0.f);
    float4 e3 = make_float4(0.f, 0.f, 0.f, 0.f);

    #pragma unroll
    for (int c = 0; c < CHUNKS; c += 4) {
        float4 v0 = pp[(size_t)(c + 0) * (DD / 4) + t];
        float4 v1 = pp[(size_t)(c + 1) * (DD / 4) + t];
        float4 v2 = pp[(size_t)(c + 2) * (DD / 4) + t];
        float4 v3 = pp[(size_t)(c + 3) * (DD / 4) + t];
        e0.x += v0.x; e0.y += v0.y; e0.z += v0.z; e0.w += v0.w;
        e1.x += v1.x; e1.y += v1.y; e1.z += v1.z; e1.w += v1.w;
        e2.x += v2.x; e2.y += v2.y; e2.z += v2.z; e2.w += v2.w;
        e3.x += v3.x; e3.y += v3.y; e3.z += v3.z; e3.w += v3.w;
    }

    float4 acc;
    acc.x = (e0.x + e1.x) + (e2.x + e3.x);
    acc.y = (e0.y + e1.y) + (e2.y + e3.y);
    acc.z = (e0.z + e1.z) + (e2.z + e3.z);
    acc.w = (e0.w + e1.w) + (e2.w + e3.w);

    reinterpret_cast<float4*>(g_xsum + (size_t)b * DD)[t] = acc;
}

// ---------------------------------------------------------------------------
// Kernel C: out[b, e] = dot(xsum[b,:], Wv[e,:]) + S * bv[e]
// grid = 128 CTAs, block = 256 (8 warps); warp owns row e = cta*8 + warp.
// NO smem stage: all 72 operand float4s per warp (8 Wv + 64 xsum) have
// addresses known at entry; xsum (32 KB) becomes L1-resident per SM, Wv is
// streamed from L2 exactly once. Compiler front-batches the LDGs (high MLP),
// no __syncthreads barrier, no serial prologue.
// ---------------------------------------------------------------------------
__global__ __launch_bounds__(256) void gemv_kernel(const float* __restrict__ Wv,
                                                   const float* __restrict__ bv,
                                                   float* __restrict__ out) {
    const int t = threadIdx.x;
    const int warp = t >> 5;
    const int lane = t & 31;
    const int e = blockIdx.x * 8 + warp;

    const float4* __restrict__ wrow = reinterpret_cast<const float4*>(Wv + (size_t)e * DD);
    const float4* __restrict__ xsv  = reinterpret_cast<const float4*>(g_xsum);

    float s0 = 0.f, s1 = 0.f, s2 = 0.f, s3 = 0.f;
    float s4 = 0.f, s5 = 0.f, s6 = 0.f, s7 = 0.f;

    #pragma unroll
    for (int i = 0; i < 8; ++i) {          // lane covers float4 cols lane + 32*i
        const int c4 = lane + 32 * i;
        float4 w = wrow[c4];
        #define ACC(bi, s) { \
            float4 xv = xsv[(bi) * (DD / 4) + c4]; \
            s += w.x * xv.x + w.y * xv.y + w.z * xv.z + w.w * xv.w; }
        ACC(0, s0) ACC(1, s1) ACC(2, s2) ACC(3, s3)
        ACC(4, s4) ACC(5, s5) ACC(6, s6) ACC(7, s7)
        #undef ACC
    }

    #pragma unroll
    for (int off = 16; off; off >>= 1) {
        s0 += __shfl_xor_sync(0xffffffffu, s0, off);
        s1 += __shfl_xor_sync(0xffffffffu, s1, off);
        s2 += __shfl_xor_sync(0xffffffffu, s2, off);
        s3 += __shfl_xor_sync(0xffffffffu, s3, off);
        s4 += __shfl_xor_sync(0xffffffffu, s4, off);
        s5 += __shfl_xor_sync(0xffffffffu, s5, off);
        s6 += __shfl_xor_sync(0xffffffffu, s6, off);
        s7 += __shfl_xor_sync(0xffffffffu, s7, off);
    }

    if (lane == 0) {
        const float bias = (float)SS * bv[e];
        out[0 * DD + e] = s0 + bias;
        out[1 * DD + e] = s1 + bias;
        out[2 * DD + e] = s2 + bias;
        out[3 * DD + e] = s3 + bias;
        out[4 * DD + e] = s4 + bias;
        out[5 * DD + e] = s5 + bias;
        out[6 * DD + e] = s6 + bias;
        out[7 * DD + e] = s7 + bias;
    }
}

// ---------------------------------------------------------------------------
// kernel_launch — graph-capturable, allocation-free, deterministic.
// Input order (metadata): 0=x, 1=Wq, 2=bq, 3=Wk, 4=bk, 5=Wv, 6=bv
// ---------------------------------------------------------------------------
extern "C" void kernel_launch(void* const* d_in, const int* in_sizes, int n_in,
                              void* d_out, int out_size) {
    (void)in_sizes; (void)n_in; (void)out_size;
    const float* x  = (const float*)d_in[0];
    const float* Wv = (const float*)d_in[5];
    const float* bv = (const float*)d_in[6];
    float* out = (float*)d_out;

    colsum_kernel<<<dim3(CHUNKS, BB), 256>>>(x);
    reduce_kernel<<<BB, 256>>>();
    gemv_kernel<<<DD / 8, 256>>>(Wv, bv, out);
}

// round 7
// speedup vs baseline: 1.8017x; 1.8017x over previous
#include <cuda_runtime.h>

// Problem constants (fixed by the reference: B=8, S=2048, D=1024)
#define BB 8
#define SS 2048
#define DD 1024
#define CHUNKS 64
#define ROWS_PER_CHUNK (SS / CHUNKS)   // 32

// Scratch (written, never accumulated -> no zero-init needed).
__device__ float g_partial[BB * CHUNKS * DD];   // 2 MB
__device__ float g_xsum[BB * DD];               // 32 KB

// ---------------------------------------------------------------------------
// Kernel A: per-(batch, chunk) column sum of x over S.
// grid = (64, 8) = 512 CTAs, block = 256; thread t owns float4 column t.
// 8-row load groups -> 8 independent LDG.128 in flight per warp (MLP=8),
// folded into 4 accumulators to bound register pressure (~60 regs).
// ---------------------------------------------------------------------------
__global__ __launch_bounds__(256) void colsum_kernel(const float* __restrict__ x) {
    const int c = blockIdx.x;
    const int b = blockIdx.y;
    const int t = threadIdx.x;

    const float4* __restrict__ xp =
        reinterpret_cast<const float4*>(x + ((size_t)b * SS + (size_t)c * ROWS_PER_CHUNK) * DD) + t;

    float4 a0 = make_float4(0.f, 0.f, 0.f, 0.f);
    float4 a1 = make_float4(0.f, 0.f, 0.f, 0.f);
    float4 a2 = make_float4(0.f, 0.f, 0.f, 0.f);
    float4 a3 = make_float4(0.f, 0.f, 0.f, 0.f);

    #pragma unroll
    for (int s = 0; s < ROWS_PER_CHUNK; s += 8) {
        // 8 loads issued back-to-back before any dependent FADD.
        float4 v0 = xp[(size_t)(s + 0) * (DD / 4)];
        float4 v1 = xp[(size_t)(s + 1) * (DD / 4)];
        float4 v2 = xp[(size_t)(s + 2) * (DD / 4)];
        float4 v3 = xp[(size_t)(s + 3) * (DD / 4)];
        float4 v4 = xp[(size_t)(s + 4) * (DD / 4)];
        float4 v5 = xp[(size_t)(s + 5) * (DD / 4)];
        float4 v6 = xp[(size_t)(s + 6) * (DD / 4)];
        float4 v7 = xp[(size_t)(s + 7) * (DD / 4)];
        a0.x += v0.x; a0.y += v0.y; a0.z += v0.z; a0.w += v0.w;
        a1.x += v1.x; a1.y += v1.y; a1.z += v1.z; a1.w += v1.w;
        a2.x += v2.x; a2.y += v2.y; a2.z += v2.z; a2.w += v2.w;
        a3.x += v3.x; a3.y += v3.y; a3.z += v3.z; a3.w += v3.w;
        a0.x += v4.x; a0.y += v4.y; a0.z += v4.z; a0.w += v4.w;
        a1.x += v5.x; a1.y += v5.y; a1.z += v5.z; a1.w += v5.w;
        a2.x += v6.x; a2.y += v6.y; a2.z += v6.z; a2.w += v6.w;
        a3.x += v7.x; a3.y += v7.y; a3.z += v7.z; a3.w += v7.w;
    }

    float4 acc;
    acc.x = (a0.x + a1.x) + (a2.x + a3.x);
    acc.y = (a0.y + a1.y) + (a2.y + a3.y);
    acc.z = (a0.z + a1.z) + (a2.z + a3.z);
    acc.w = (a0.w + a1.w) + (a2.w + a3.w);

    reinterpret_cast<float4*>(g_partial + ((size_t)b * CHUNKS + c) * DD)[t] = acc;
}

// ---------------------------------------------------------------------------
// Kernel B: fold the 64 chunk partials into g_xsum.
// grid = (8 col-groups, 8 batches) = 64 CTAs, block = 256.
//   tx = t & 31  -> float4 column within group (cg*32 + tx)
//   ty = t >> 5  -> chunk sub-group: thread sums chunks [ty*8, ty*8+8)
// Each thread issues its 8 loads in one batch (one latency wave), partials
// folded through a 4 KB smem tree in fixed order (deterministic).
// ---------------------------------------------------------------------------
__global__ __launch_bounds__(256) void reduce_kernel() {
    __shared__ float4 red[8][32];

    const int cg = blockIdx.x;      // column group: float4 cols [cg*32, cg*32+32)
    const int b  = blockIdx.y;
    const int tx = threadIdx.x & 31;
    const int ty = threadIdx.x >> 5;

    const int c4 = cg * 32 + tx;    // this thread's float4 column
    const float4* __restrict__ pp =
        reinterpret_cast<const float4*>(g_partial + (size_t)b * CHUNKS * DD) + c4;

    float4 v0 = pp[(size_t)(ty * 8 + 0) * (DD / 4)];
    float4 v1 = pp[(size_t)(ty * 8 + 1) * (DD / 4)];
    float4 v2 = pp[(size_t)(ty * 8 + 2) * (DD / 4)];
    float4 v3 = pp[(size_t)(ty * 8 + 3) * (DD / 4)];
    float4 v4 = pp[(size_t)(ty * 8 + 4) * (DD / 4)];
    float4 v5 = pp[(size_t)(ty * 8 + 5) * (DD / 4)];
    float4 v6 = pp[(size_t)(ty * 8 + 6) * (DD / 4)];
    float4 v7 = pp[(size_t)(ty * 8 + 7) * (DD / 4)];

    float4 a;
    a.x = ((v0.x + v1.x) + (v2.x + v3.x)) + ((v4.x + v5.x) + (v6.x + v7.x));
    a.y = ((v0.y + v1.y) + (v2.y + v3.y)) + ((v4.y + v5.y) + (v6.y + v7.y));
    a.z = ((v0.z + v1.z) + (v2.z + v3.z)) + ((v4.z + v5.z) + (v6.z + v7.z));
    a.w = ((v0.w + v1.w) + (v2.w + v3.w)) + ((v4.w + v5.w) + (v6.w + v7.w));

    red[ty][tx] = a;
    __syncthreads();

    if (ty == 0) {
        float4 r0 = red[0][tx], r1 = red[1][tx], r2 = red[2][tx], r3 = red[3][tx];
        float4 r4 = red[4][tx], r5 = red[5][tx], r6 = red[6][tx], r7 = red[7][tx];
        float4 s;
        s.x = ((r0.x + r1.x) + (r2.x + r3.x)) + ((r4.x + r5.x) + (r6.x + r7.x));
        s.y = ((r0.y + r1.y) + (r2.y + r3.y)) + ((r4.y + r5.y) + (r6.y + r7.y));
        s.z = ((r0.z + r1.z) + (r2.z + r3.z)) + ((r4.z + r5.z) + (r6.z + r7.z));
        s.w = ((r0.w + r1.w) + (r2.w + r3.w)) + ((r4.w + r5.w) + (r6.w + r7.w));
        reinterpret_cast<float4*>(g_xsum + (size_t)b * DD)[c4] = s;
    }
}

// ---------------------------------------------------------------------------
// Kernel C: out[b, e] = dot(xsum[b,:], Wv[e,:]) + S * bv[e]
// grid = 128 CTAs, block = 256 (8 warps). Each CTA:
//   stage 1: load ALL 8 batches' xsum into smem (32 KB) — 4 MB L2 total.
//   stage 2: each warp owns one Wv row (e = cta*8 + warp), reads it ONCE,
//            and dots against all 8 batches (8 accumulators per lane).
// (Reverted to the measured-good smem-staged version.)
// ---------------------------------------------------------------------------
__global__ __launch_bounds__(256) void gemv_kernel(const float* __restrict__ Wv,
                                                   const float* __restrict__ bv,
                                                   float* __restrict__ out) {
    __shared__ float xs[BB * DD];   // 32 KB

    const int t = threadIdx.x;

    // Stage 1: cooperative load of all 8 xsum vectors (2048 float4)
    {
        const float4* __restrict__ src = reinterpret_cast<const float4*>(g_xsum);
        float4*       __restrict__ dst = reinterpret_cast<float4*>(xs);
        #pragma unroll
        for (int i = 0; i < (BB * DD / 4) / 256; ++i)   // 8 iterations
            dst[t + 256 * i] = src[t + 256 * i];
    }
    __syncthreads();

    const int warp = t >> 5;
    const int lane = t & 31;
    const int e = blockIdx.x * 8 + warp;   // output feature owned by this warp

    const float4* __restrict__ wrow = reinterpret_cast<const float4*>(Wv + (size_t)e * DD);

    float s0 = 0.f, s1 = 0.f, s2 = 0.f, s3 = 0.f;
    float s4 = 0.f, s5 = 0.f, s6 = 0.f, s7 = 0.f;

    #pragma unroll
    for (int i = 0; i < 8; ++i) {           // lane covers float4 cols lane + 32*i
        const int c4 = lane + 32 * i;
        float4 w = wrow[c4];
        #define ACC(bi, s) { \
            float4 xv = reinterpret_cast<const float4*>(xs + (bi) * DD)[c4]; \
            s += w.x * xv.x + w.y * xv.y + w.z * xv.z + w.w * xv.w; }
        ACC(0, s0) ACC(1, s1) ACC(2, s2) ACC(3, s3)
        ACC(4, s4) ACC(5, s5) ACC(6, s6) ACC(7, s7)
        #undef ACC
    }

    #pragma unroll
    for (int off = 16; off; off >>= 1) {
        s0 += __shfl_xor_sync(0xffffffffu, s0, off);
        s1 += __shfl_xor_sync(0xffffffffu, s1, off);
        s2 += __shfl_xor_sync(0xffffffffu, s2, off);
        s3 += __shfl_xor_sync(0xffffffffu, s3, off);
        s4 += __shfl_xor_sync(0xffffffffu, s4, off);
        s5 += __shfl_xor_sync(0xffffffffu, s5, off);
        s6 += __shfl_xor_sync(0xffffffffu, s6, off);
        s7 += __shfl_xor_sync(0xffffffffu, s7, off);
    }

    if (lane == 0) {
        const float bias = (float)SS * bv[e];
        out[0 * DD + e] = s0 + bias;
        out[1 * DD + e] = s1 + bias;
        out[2 * DD + e] = s2 + bias;
        out[3 * DD + e] = s3 + bias;
        out[4 * DD + e] = s4 + bias;
        out[5 * DD + e] = s5 + bias;
        out[6 * DD + e] = s6 + bias;
        out[7 * DD + e] = s7 + bias;
    }
}

// ---------------------------------------------------------------------------
// kernel_launch — graph-capturable, allocation-free, deterministic.
// Input order (metadata): 0=x, 1=Wq, 2=bq, 3=Wk, 4=bk, 5=Wv, 6=bv
// ---------------------------------------------------------------------------
extern "C" void kernel_launch(void* const* d_in, const int* in_sizes, int n_in,
                              void* d_out, int out_size) {
    (void)in_sizes; (void)n_in; (void)out_size;
    const float* x  = (const float*)d_in[0];
    const float* Wv = (const float*)d_in[5];
    const float* bv = (const float*)d_in[6];
    float* out = (float*)d_out;

    colsum_kernel<<<dim3(CHUNKS, BB), 256>>>(x);
    reduce_kernel<<<dim3(8, BB), 256>>>();
    gemv_kernel<<<DD / 8, 256>>>(Wv, bv, out);
}